// round 1
// baseline (speedup 1.0000x reference)
#include <cuda_runtime.h>
#include <cstdint>

// ============================================================================
// FloReLBlock: FFJORD-style CNF with RK-3/8 integration + Hutchinson trace.
// B=2048, D=512, H=1024, 9 steps x 4 stages, TRACE_STEPS=2.
//
// Per stage (state z = s[:, :D], time t):
//   h   = tanh(z @ W1 + b1 + t*tw1)                       (B x H)
//   f   = h @ W2 + b2                                     (B x D)
//   div = (1/2) sum_i sum_j (e_i@W1)[b,j]*(1-h^2)[b,j]*(e_i@W2^T)[b,j], clip 100
//   k   = [f, -div]
// e_i are exact JAX threefry Rademacher draws.
// ============================================================================

#define JAX_PARTITIONABLE 1   // modern jax default; flip to 0 for legacy RNG

constexpr int Bn  = 2048;
constexpr int Dn  = 512;
constexpr int Hn  = 1024;
constexpr int DP1 = Dn + 1;
constexpr int H2  = 2 * Hn;

// -------------------- device scratch (static, no allocation) ----------------
__device__ float g_state  [Bn * DP1];
__device__ float g_stageIn[Bn * DP1];
__device__ float g_h      [Bn * Hn];
__device__ float g_e      [2 * Bn * Dn];
__device__ float g_P      [2 * Bn * H2];
__device__ float g_Wcat   [Dn * H2];
__device__ float g_k1     [Bn * DP1];
__device__ float g_k2     [Bn * DP1];
__device__ float g_k3     [Bn * DP1];
__device__ float g_k4     [Bn * DP1];

__device__ __forceinline__ float* bufsel(int id) {
    switch (id) {
        case 0: return g_state;
        case 1: return g_stageIn;
        case 2: return g_h;
        case 3: return g_e;
        case 4: return g_P;
        case 5: return g_Wcat;
        case 6: return g_k1;
        case 7: return g_k2;
        case 8: return g_k3;
        default: return g_k4;
    }
}

// -------------------- threefry2x32 (exact JAX) ------------------------------
__host__ __device__ __forceinline__ void tf2x32(
    uint32_t k0, uint32_t k1, uint32_t x0, uint32_t x1,
    uint32_t& o0, uint32_t& o1)
{
    const uint32_t ks0 = k0;
    const uint32_t ks1 = k1;
    const uint32_t ks2 = 0x1BD11BDAu ^ k0 ^ k1;
    x0 += ks0; x1 += ks1;
#define TFR(r) { x0 += x1; x1 = (x1 << (r)) | (x1 >> (32 - (r))); x1 ^= x0; }
    TFR(13) TFR(15) TFR(26) TFR(6)
    x0 += ks1; x1 += ks2 + 1u;
    TFR(17) TFR(29) TFR(16) TFR(24)
    x0 += ks2; x1 += ks0 + 2u;
    TFR(13) TFR(15) TFR(26) TFR(6)
    x0 += ks0; x1 += ks1 + 3u;
    TFR(17) TFR(29) TFR(16) TFR(24)
    x0 += ks1; x1 += ks2 + 4u;
    TFR(13) TFR(15) TFR(26) TFR(6)
    x0 += ks2; x1 += ks0 + 5u;
#undef TFR
    o0 = x0; o1 = x1;
}

// -------------------- reductions --------------------------------------------
__device__ __forceinline__ float blockReduceSum256(float v) {
    __shared__ float sh[8];
    #pragma unroll
    for (int o = 16; o > 0; o >>= 1) v += __shfl_down_sync(0xffffffffu, v, o);
    const int lane = threadIdx.x & 31;
    const int w    = threadIdx.x >> 5;
    if (lane == 0) sh[w] = v;
    __syncthreads();
    if (w == 0) {
        v = (lane < 8) ? sh[lane] : 0.f;
        #pragma unroll
        for (int o = 4; o > 0; o >>= 1) v += __shfl_down_sync(0xffffffffu, v, o);
    }
    return v;  // valid on thread 0
}

// -------------------- small kernels -----------------------------------------
__global__ void __launch_bounds__(256) init_state_kernel(const float* __restrict__ x) {
    int i = blockIdx.x * 256 + threadIdx.x;
    if (i < Bn * DP1) {
        int b = i / DP1, c = i % DP1;
        g_state[i] = (c < Dn) ? x[b * Dn + c] : 0.f;
    }
}

// Wcat = [W1 | W2^T]  (D x 2H)
__global__ void __launch_bounds__(256) build_wcat_kernel(
    const float* __restrict__ W1, const float* __restrict__ W2)
{
    int i = blockIdx.x * 256 + threadIdx.x;
    if (i < Dn * Hn) {
        int d = i / Hn, j = i % Hn;
        g_Wcat[d * H2 + j]      = W1[i];               // e@W1 half
        g_Wcat[d * H2 + Hn + j] = W2[j * Dn + d];      // e@W2^T half
    }
}

// Generate e0, e1 (Rademacher) for one stage from the two "lower" keys.
__global__ void __launch_bounds__(256) rng_kernel(
    uint32_t a0, uint32_t b0, uint32_t a1, uint32_t b1)
{
#if JAX_PARTITIONABLE
    int j = blockIdx.x * 256 + threadIdx.x;
    if (j < Bn * Dn) {
        uint32_t o0, o1;
        tf2x32(a0, b0, 0u, (uint32_t)j, o0, o1);
        g_e[j] = (((o0 ^ o1) & 1u) != 0u) ? 1.f : -1.f;
        tf2x32(a1, b1, 0u, (uint32_t)j, o0, o1);
        g_e[Bn * Dn + j] = (((o0 ^ o1) & 1u) != 0u) ? 1.f : -1.f;
    }
#else
    const int N2 = (Bn * Dn) / 2;
    int j = blockIdx.x * 256 + threadIdx.x;
    if (j < N2) {
        uint32_t o0, o1;
        tf2x32(a0, b0, (uint32_t)j, (uint32_t)(N2 + j), o0, o1);
        g_e[j]      = ((o0 & 1u) != 0u) ? 1.f : -1.f;
        g_e[N2 + j] = ((o1 & 1u) != 0u) ? 1.f : -1.f;
        tf2x32(a1, b1, (uint32_t)j, (uint32_t)(N2 + j), o0, o1);
        g_e[Bn * Dn + j]      = ((o0 & 1u) != 0u) ? 1.f : -1.f;
        g_e[Bn * Dn + N2 + j] = ((o1 & 1u) != 0u) ? 1.f : -1.f;
    }
#endif
}

// stageIn = state + c1*k1 + c2*k2 + c3*k3
__global__ void __launch_bounds__(256) prep_kernel(float c1, float c2, float c3) {
    int i = blockIdx.x * 256 + threadIdx.x;
    if (i < Bn * DP1)
        g_stageIn[i] = g_state[i] + c1 * g_k1[i] + c2 * g_k2[i] + c3 * g_k3[i];
}

// state += w * (k1 + 3*(k2+k3) + k4),  w = dt/8
__global__ void __launch_bounds__(256) update_kernel(float w) {
    int i = blockIdx.x * 256 + threadIdx.x;
    if (i < Bn * DP1)
        g_state[i] += w * (g_k1[i] + 3.f * (g_k2[i] + g_k3[i]) + g_k4[i]);
}

// div over both samples, write -clip(div/2) into k[:, D]
__global__ void __launch_bounds__(256) div_reduce_kernel(int kid) {
    const int b = blockIdx.x;
    const float* P0 = g_P + (size_t)b * H2;
    const float* P1 = g_P + (size_t)(b + Bn) * H2;
    const float* hr = g_h + (size_t)b * Hn;
    float acc = 0.f;
    for (int j = threadIdx.x; j < Hn; j += 256) {
        float hh = hr[j];
        float w  = 1.f - hh * hh;
        acc += w * (P0[j] * P0[Hn + j] + P1[j] * P1[Hn + j]);
    }
    float tot = blockReduceSum256(acc);
    if (threadIdx.x == 0) {
        float d = tot * 0.5f;
        d = fminf(fmaxf(d, -100.f), 100.f);
        bufsel(kid)[(size_t)b * DP1 + Dn] = -d;
    }
}

// out[0 : B*D) = rep,  out[B*D + b] = -0.5*||rep_b||^2 + probsolve_b
__global__ void __launch_bounds__(256) finalize_kernel(float* __restrict__ out) {
    const int b = blockIdx.x;
    const float* row = g_state + (size_t)b * DP1;
    float acc = 0.f;
    for (int d = threadIdx.x; d < Dn; d += 256) {
        float v = row[d];
        out[(size_t)b * Dn + d] = v;
        acc += v * v;
    }
    float tot = blockReduceSum256(acc);
    if (threadIdx.x == 0)
        out[(size_t)Bn * Dn + b] = -0.5f * tot + row[Dn];
}

// -------------------- tiled SGEMM -------------------------------------------
// C[MxN] = A[MxK] @ B[KxN] (+ epilogue). Row-major, arbitrary lda (scalar A
// loads), vectorized B loads. MODE 0: plain; 1: tanh(acc + bias + t*tvec);
// 2: acc + bias.
template <int BM, int BN, int TM, int TN, int MODE>
__global__ void __launch_bounds__(256) gemm_kernel(
    int Aid, int lda, const float* __restrict__ Bext, int Bid, int ldb,
    int Cid, int ldc, int M, int N, int K,
    const float* __restrict__ bias, const float* __restrict__ tvec, float t)
{
    constexpr int BK = 16;
    __shared__ __align__(16) float As[BK][BM + 4];
    __shared__ __align__(16) float Bs[BK][BN];

    const float* A  = bufsel(Aid);
    const float* Bm = Bext ? Bext : bufsel(Bid);
    float*       C  = bufsel(Cid);

    const int tid = threadIdx.x;
    constexpr int TX = BN / TN;   // threads along N
    const int tx = tid % TX;
    const int ty = tid / TX;
    const int m0 = blockIdx.y * BM;
    const int n0 = blockIdx.x * BN;

    float acc[TM][TN];
    #pragma unroll
    for (int i = 0; i < TM; ++i)
        #pragma unroll
        for (int j = 0; j < TN; ++j) acc[i][j] = 0.f;

    for (int kt = 0; kt < K; kt += BK) {
        #pragma unroll
        for (int it = 0; it < (BM * BK) / 256; ++it) {
            int idx = tid + it * 256;
            int k = idx & (BK - 1);
            int m = idx >> 4;
            As[k][m] = A[(size_t)(m0 + m) * lda + kt + k];
        }
        #pragma unroll
        for (int it = 0; it < (BK * BN) / 1024; ++it) {
            int idx = (tid + it * 256) * 4;
            int k = idx / BN;
            int n = idx % BN;
            *(float4*)&Bs[k][n] = *(const float4*)&Bm[(size_t)(kt + k) * ldb + n0 + n];
        }
        __syncthreads();
        #pragma unroll
        for (int k = 0; k < BK; ++k) {
            float ra[TM], rb[TN];
            #pragma unroll
            for (int i = 0; i < TM; i += 4)
                *(float4*)&ra[i] = *(const float4*)&As[k][ty * TM + i];
            #pragma unroll
            for (int j = 0; j < TN; j += 4)
                *(float4*)&rb[j] = *(const float4*)&Bs[k][tx * TN + j];
            #pragma unroll
            for (int i = 0; i < TM; ++i)
                #pragma unroll
                for (int j = 0; j < TN; ++j)
                    acc[i][j] += ra[i] * rb[j];
        }
        __syncthreads();
    }

    #pragma unroll
    for (int i = 0; i < TM; ++i) {
        int m = m0 + ty * TM + i;
        #pragma unroll
        for (int j = 0; j < TN; ++j) {
            int n = n0 + tx * TN + j;
            float v = acc[i][j];
            if (MODE == 1)      v = tanhf(v + bias[n] + t * tvec[n]);
            else if (MODE == 2) v = v + bias[n];
            C[(size_t)m * ldc + n] = v;
        }
    }
}

// -------------------- host-side key schedule --------------------------------
struct KP { uint32_t a, b; };

static inline KP h_tf(KP k, uint32_t x0, uint32_t x1) {
    KP r; tf2x32(k.a, k.b, x0, x1, r.a, r.b); return r;
}

static inline void split5(KP key, KP out[5]) {
#if JAX_PARTITIONABLE
    for (uint32_t j = 0; j < 5; ++j) out[j] = h_tf(key, 0u, j);
#else
    uint32_t y0[5], y1[5];
    for (uint32_t i = 0; i < 5; ++i) tf2x32(key.a, key.b, i, 5u + i, y0[i], y1[i]);
    uint32_t w[10] = { y0[0], y0[1], y0[2], y0[3], y0[4],
                       y1[0], y1[1], y1[2], y1[3], y1[4] };
    for (int j = 0; j < 5; ++j) out[j] = KP{ w[2 * j], w[2 * j + 1] };
#endif
}

// lower key for randint(fold_in(kq, i), ..., 0, 2): split(folded, 2)[1]
static inline KP lower_key(KP kq, uint32_t i) {
    KP folded = h_tf(kq, 0u, i);   // fold_in: counter (0, i) in both modes
#if JAX_PARTITIONABLE
    return h_tf(folded, 0u, 1u);
#else
    uint32_t a0, b0, a1, b1;
    tf2x32(folded.a, folded.b, 0u, 2u, a0, b0);
    tf2x32(folded.a, folded.b, 1u, 3u, a1, b1);
    // flat out = [a0, a1, b0, b1]; keys: hi=(a0,a1), lo=(b0,b1)
    return KP{ b0, b1 };
#endif
}

// -------------------- launcher ----------------------------------------------
extern "C" void kernel_launch(void* const* d_in, const int* in_sizes, int n_in,
                              void* d_out, int out_size)
{
    (void)in_sizes; (void)n_in; (void)out_size;
    const float* x   = (const float*)d_in[0];
    const float* W1  = (const float*)d_in[1];
    const float* b1  = (const float*)d_in[2];
    const float* tw1 = (const float*)d_in[3];
    const float* W2  = (const float*)d_in[4];
    const float* b2  = (const float*)d_in[5];
    float* out = (float*)d_out;

    const int GRID_E = (Bn * DP1 + 255) / 256;        // 4104

    init_state_kernel<<<GRID_E, 256>>>(x);
    build_wcat_kernel<<<(Dn * Hn + 255) / 256, 256>>>(W1, W2);

    // t grid mirrors jnp.linspace(0, 1, 10) in fp32
    const float step = (float)(1.0 / 9.0);
    KP key{ 0u, 1234u };

    for (int s = 0; s < 9; ++s) {
        const float t0 = (float)s * step;
        const float t1 = (float)(s + 1) * step;
        const float dt = t1 - t0;
        KP ks5[5];
        split5(key, ks5);
        key = ks5[0];
        const float tst[4] = { t0, t0 + dt / 3.0f, t0 + dt * 2.0f / 3.0f, t1 };

        for (int st = 0; st < 4; ++st) {
            KP kq = ks5[1 + st];
            KP l0 = lower_key(kq, 0u);
            KP l1 = lower_key(kq, 1u);
#if JAX_PARTITIONABLE
            rng_kernel<<<(Bn * Dn + 255) / 256, 256>>>(l0.a, l0.b, l1.a, l1.b);
#else
            rng_kernel<<<(Bn * Dn / 2 + 255) / 256, 256>>>(l0.a, l0.b, l1.a, l1.b);
#endif
            if (st == 1) prep_kernel<<<GRID_E, 256>>>(dt / 3.f, 0.f, 0.f);
            if (st == 2) prep_kernel<<<GRID_E, 256>>>(-dt / 3.f, dt, 0.f);
            if (st == 3) prep_kernel<<<GRID_E, 256>>>(dt, -dt, dt);

            const int Aid = (st == 0) ? 0 : 1;     // state or stageIn
            const int kid = 6 + st;                // k1..k4

            // h = tanh(z @ W1 + b1 + t*tw1)
            gemm_kernel<128, 128, 8, 8, 1>
                <<<dim3(Hn / 128, Bn / 128), 256>>>(
                    Aid, DP1, W1, -1, Hn, 2, Hn, Bn, Hn, Dn, b1, tw1, tst[st]);

            // P = [e0;e1] @ [W1 | W2^T]
            gemm_kernel<128, 128, 8, 8, 0>
                <<<dim3(H2 / 128, 2 * Bn / 128), 256>>>(
                    3, Dn, nullptr, 5, H2, 4, H2, 2 * Bn, H2, Dn,
                    nullptr, nullptr, 0.f);

            // f = h @ W2 + b2  ->  k[:, 0:D]
            gemm_kernel<64, 64, 4, 4, 2>
                <<<dim3(Dn / 64, Bn / 64), 256>>>(
                    2, Hn, W2, -1, Dn, kid, DP1, Bn, Dn, Hn,
                    b2, nullptr, 0.f);

            // k[:, D] = -clip((div0+div1)/2)
            div_reduce_kernel<<<Bn, 256>>>(kid);
        }
        update_kernel<<<GRID_E, 256>>>(dt * 0.125f);
    }

    finalize_kernel<<<Bn, 256>>>(out);
}

// round 3
// speedup vs baseline: 3.1161x; 3.1161x over previous
#include <cuda_runtime.h>
#include <cuda_bf16.h>
#include <cstdint>

// ============================================================================
// FloReLBlock via mma.sync (HMMA) split-bf16 GEMMs. tcgen05 is NOT available
// under this harness (PTX targets compute_103 without 'a'), so we use the
// portable tensor-core path: ldmatrix + mma.sync.m16n8k16.bf16, fp32 accum.
//
// B=2048, D=512, H=1024, 9 RK-3/8 steps x 4 stages, TRACE_STEPS=2.
//   h   = tanh(z @ W1 + b1 + t*tw1)
//   f   = h @ W2 + b2
//   div = (1/2) sum (e@W1)*(1-h^2)*(e@W2^T), clip 100  (fused into GEMM2)
// Split-bf16: v = hi + lo;  A@B ~= Ah@Bh + Ah@Bl + Al@Bh  (e is exact in bf16
// so GEMM2 needs only 2 terms).
// ============================================================================

constexpr int Bn  = 2048;
constexpr int Dn  = 512;
constexpr int Hn  = 1024;
constexpr int DP1 = Dn + 1;

// -------------------- device scratch ----------------------------------------
__device__ float g_state[Bn * DP1];
__device__ float g_kbuf[4][Bn * DP1];
__device__ float g_h[Bn * Hn];
__device__ float g_div[2 * Bn];

__device__ __align__(16) __nv_bfloat16 g_z_hi[Bn * Dn];
__device__ __align__(16) __nv_bfloat16 g_z_lo[Bn * Dn];
__device__ __align__(16) __nv_bfloat16 g_e   [2 * Bn * Dn];
__device__ __align__(16) __nv_bfloat16 g_h_hi[Bn * Hn];
__device__ __align__(16) __nv_bfloat16 g_h_lo[Bn * Hn];
__device__ __align__(16) __nv_bfloat16 g_W1T_hi[Hn * Dn];      // [H x D] row-major (N x K)
__device__ __align__(16) __nv_bfloat16 g_W1T_lo[Hn * Dn];
__device__ __align__(16) __nv_bfloat16 g_Wc_hi[2 * Hn * Dn];   // interleaved: row 2j=W1T[j], 2j+1=W2[j]
__device__ __align__(16) __nv_bfloat16 g_Wc_lo[2 * Hn * Dn];
__device__ __align__(16) __nv_bfloat16 g_W2T_hi[Dn * Hn];      // [D x H] row-major (N x K)
__device__ __align__(16) __nv_bfloat16 g_W2T_lo[Dn * Hn];

// -------------------- threefry2x32 (exact JAX, partitionable) ---------------
__host__ __device__ __forceinline__ void tf2x32(
    uint32_t k0, uint32_t k1, uint32_t x0, uint32_t x1,
    uint32_t& o0, uint32_t& o1)
{
    const uint32_t ks0 = k0;
    const uint32_t ks1 = k1;
    const uint32_t ks2 = 0x1BD11BDAu ^ k0 ^ k1;
    x0 += ks0; x1 += ks1;
#define TFR(r) { x0 += x1; x1 = (x1 << (r)) | (x1 >> (32 - (r))); x1 ^= x0; }
    TFR(13) TFR(15) TFR(26) TFR(6)
    x0 += ks1; x1 += ks2 + 1u;
    TFR(17) TFR(29) TFR(16) TFR(24)
    x0 += ks2; x1 += ks0 + 2u;
    TFR(13) TFR(15) TFR(26) TFR(6)
    x0 += ks0; x1 += ks1 + 3u;
    TFR(17) TFR(29) TFR(16) TFR(24)
    x0 += ks1; x1 += ks2 + 4u;
    TFR(13) TFR(15) TFR(26) TFR(6)
    x0 += ks2; x1 += ks0 + 5u;
#undef TFR
    o0 = x0; o1 = x1;
}

// -------------------- helpers -----------------------------------------------
__device__ __forceinline__ void split2(float v, __nv_bfloat16& hi, __nv_bfloat16& lo) {
    hi = __float2bfloat16(v);
    lo = __float2bfloat16(v - __bfloat162float(hi));
}

__device__ __forceinline__ uint32_t smem_u32(const void* p) {
    uint32_t a;
    asm("{ .reg .u64 t; cvta.to.shared.u64 t, %1; cvt.u32.u64 %0, t; }" : "=r"(a) : "l"(p));
    return a;
}

__device__ __forceinline__ void cpasync16(uint32_t dst, const void* src) {
    asm volatile("cp.async.cg.shared.global [%0], [%1], 16;" :: "r"(dst), "l"(src));
}
#define CP_COMMIT() asm volatile("cp.async.commit_group;" ::: "memory")

__device__ __forceinline__ uint32_t swz(uint32_t x) {   // SW128-style xor swizzle
    return x ^ ((x >> 3) & 0x70u);
}

__device__ __forceinline__ void ldsm_x4(uint32_t& r0, uint32_t& r1, uint32_t& r2, uint32_t& r3, uint32_t addr) {
    asm volatile("ldmatrix.sync.aligned.m8n8.x4.shared.b16 {%0,%1,%2,%3}, [%4];"
                 : "=r"(r0), "=r"(r1), "=r"(r2), "=r"(r3) : "r"(addr));
}

__device__ __forceinline__ void mma16816(
    float& d0, float& d1, float& d2, float& d3,
    uint32_t a0, uint32_t a1, uint32_t a2, uint32_t a3,
    uint32_t b0, uint32_t b1)
{
    asm volatile(
        "mma.sync.aligned.m16n8k16.row.col.f32.bf16.bf16.f32 "
        "{%0,%1,%2,%3}, {%4,%5,%6,%7}, {%8,%9}, {%0,%1,%2,%3};"
        : "+f"(d0), "+f"(d1), "+f"(d2), "+f"(d3)
        : "r"(a0), "r"(a1), "r"(a2), "r"(a3), "r"(b0), "r"(b1));
}

// -------------------- reductions --------------------------------------------
__device__ __forceinline__ float blockReduceSum256(float v) {
    __shared__ float sh[8];
    #pragma unroll
    for (int o = 16; o > 0; o >>= 1) v += __shfl_down_sync(0xffffffffu, v, o);
    const int lane = threadIdx.x & 31;
    const int w    = threadIdx.x >> 5;
    if (lane == 0) sh[w] = v;
    __syncthreads();
    if (w == 0) {
        v = (lane < 8) ? sh[lane] : 0.f;
        #pragma unroll
        for (int o = 4; o > 0; o >>= 1) v += __shfl_down_sync(0xffffffffu, v, o);
    }
    return v;
}

// -------------------- elementwise kernels -----------------------------------
__global__ void __launch_bounds__(256) init_state_kernel(const float* __restrict__ x) {
    int i = blockIdx.x * 256 + threadIdx.x;
    if (i < Bn * DP1) {
        int b = i / DP1, c = i % DP1;
        g_state[i] = (c < Dn) ? x[b * Dn + c] : 0.f;
    }
}

__global__ void __launch_bounds__(256) prep_weights_kernel(
    const float* __restrict__ W1, const float* __restrict__ W2)
{
    int i = blockIdx.x * 256 + threadIdx.x;
    if (i < Hn * Dn) {
        int j = i / Dn, d = i % Dn;
        __nv_bfloat16 hi, lo;
        split2(W1[(size_t)d * Hn + j], hi, lo);
        g_W1T_hi[(size_t)j * Dn + d] = hi;
        g_W1T_lo[(size_t)j * Dn + d] = lo;
        g_Wc_hi[(size_t)(2 * j) * Dn + d] = hi;
        g_Wc_lo[(size_t)(2 * j) * Dn + d] = lo;
        split2(W2[(size_t)j * Dn + d], hi, lo);
        g_Wc_hi[(size_t)(2 * j + 1) * Dn + d] = hi;
        g_Wc_lo[(size_t)(2 * j + 1) * Dn + d] = lo;
        g_W2T_hi[(size_t)d * Hn + j] = hi;
        g_W2T_lo[(size_t)d * Hn + j] = lo;
    }
}

__global__ void __launch_bounds__(256) split_state_kernel() {
    int i = blockIdx.x * 256 + threadIdx.x;
    if (i < Bn * Dn) {
        int b = i / Dn, d = i % Dn;
        split2(g_state[(size_t)b * DP1 + d], g_z_hi[i], g_z_lo[i]);
    }
}

__global__ void __launch_bounds__(256) prep_split_kernel(float c1, float c2, float c3) {
    int i = blockIdx.x * 256 + threadIdx.x;
    if (i < Bn * Dn) {
        int b = i / Dn, d = i % Dn;
        int idx = b * DP1 + d;
        float v = g_state[idx] + c1 * g_kbuf[0][idx] + c2 * g_kbuf[1][idx] + c3 * g_kbuf[2][idx];
        split2(v, g_z_hi[i], g_z_lo[i]);
    }
}

__global__ void __launch_bounds__(256) rng_kernel(
    uint32_t a0, uint32_t b0, uint32_t a1, uint32_t b1)
{
    int j = blockIdx.x * 256 + threadIdx.x;
    if (j < 2 * Bn) g_div[j] = 0.f;
    if (j < Bn * Dn) {
        uint32_t o0, o1;
        tf2x32(a0, b0, 0u, (uint32_t)j, o0, o1);
        g_e[j] = __float2bfloat16((((o0 ^ o1) & 1u) != 0u) ? 1.f : -1.f);
        tf2x32(a1, b1, 0u, (uint32_t)j, o0, o1);
        g_e[Bn * Dn + j] = __float2bfloat16((((o0 ^ o1) & 1u) != 0u) ? 1.f : -1.f);
    }
}

__global__ void __launch_bounds__(256) div_fin_kernel(int kid) {
    int b = blockIdx.x * 256 + threadIdx.x;
    if (b < Bn) {
        float d = 0.5f * (g_div[b] + g_div[b + Bn]);
        d = fminf(fmaxf(d, -100.f), 100.f);
        g_kbuf[kid][(size_t)b * DP1 + Dn] = -d;
    }
}

__global__ void __launch_bounds__(256) update_kernel(float w) {
    int i = blockIdx.x * 256 + threadIdx.x;
    if (i < Bn * DP1)
        g_state[i] += w * (g_kbuf[0][i] + 3.f * (g_kbuf[1][i] + g_kbuf[2][i]) + g_kbuf[3][i]);
}

__global__ void __launch_bounds__(256) finalize_kernel(float* __restrict__ out) {
    const int b = blockIdx.x;
    const float* row = g_state + (size_t)b * DP1;
    float acc = 0.f;
    for (int d = threadIdx.x; d < Dn; d += 256) {
        float v = row[d];
        out[(size_t)b * Dn + d] = v;
        acc += v * v;
    }
    float tot = blockReduceSum256(acc);
    if (threadIdx.x == 0)
        out[(size_t)Bn * Dn + b] = -0.5f * tot + row[Dn];
}

// -------------------- mma.sync GEMM -----------------------------------------
// CTA tile 128x128, K-chunk 64, 8 warps (4M x 2N), warp tile 32x64.
// A: [M x K] row-major bf16 (hi/lo), B: [N x K] row-major bf16 (hi/lo).
// MODE 0: h = tanh(acc + b1 + t*tw1), K=512, 3 terms
// MODE 1: Hutchinson div (interleaved Wc cols), K=512, 2 terms
// MODE 2: k = acc + b2, K=1024, 3 terms
constexpr int TILE_B = 16384;  // 128 rows x 128 bytes

template <int MODE>
__global__ void __launch_bounds__(256, 1) gemm_mma(
    const float* __restrict__ bias, const float* __restrict__ tvec, float t, int kid)
{
    constexpr int K  = (MODE == 2) ? 1024 : 512;
    constexpr int NC = K / 64;
    constexpr int NT = (MODE == 1) ? 2 : 3;                  // split terms
    constexpr int NTILES = (NT == 3) ? 4 : 3;                // A0[,A1],B0,B1
    constexpr int STAGE = NTILES * TILE_B;

    extern __shared__ __align__(128) char smem[];
    const uint32_t sb = smem_u32(smem);

    const int tid = threadIdx.x;
    const int wid = tid >> 5;
    const int ln  = tid & 31;
    const int m0  = blockIdx.y * 128;
    const int n0  = blockIdx.x * 128;
    const int wm  = (wid >> 1) * 32;     // warp M offset in tile
    const int wn  = (wid & 1) * 64;      // warp N offset in tile

    const __nv_bfloat16 *A0, *A1, *B0, *B1;
    if (MODE == 0)      { A0 = g_z_hi; A1 = g_z_lo;  B0 = g_W1T_hi; B1 = g_W1T_lo; }
    else if (MODE == 1) { A0 = g_e;    A1 = nullptr; B0 = g_Wc_hi;  B1 = g_Wc_lo;  }
    else                { A0 = g_h_hi; A1 = g_h_lo;  B0 = g_W2T_hi; B1 = g_W2T_lo; }

    constexpr uint32_t offA0 = 0;
    constexpr uint32_t offA1 = (NT == 3) ? TILE_B : 0;       // unused if NT==2
    constexpr uint32_t offB0 = (NT == 3) ? 2 * TILE_B : TILE_B;
    constexpr uint32_t offB1 = offB0 + TILE_B;

    // ---- tile loader: 128 rows x 64 bf16 (=128B rows), swizzled ----
    auto ld_tile = [&](const __nv_bfloat16* g, int rbase, int kt, uint32_t toff) {
        #pragma unroll
        for (int it = 0; it < 4; ++it) {
            int idx = it * 256 + tid;
            int row = idx >> 3, u = idx & 7;
            uint32_t dst = sb + toff + swz((uint32_t)(row * 128 + u * 16));
            cpasync16(dst, (const void*)(g + (size_t)(rbase + row) * K + kt + u * 8));
        }
    };
    auto load_chunk = [&](int c, int st) {
        const int kt = c * 64;
        const uint32_t base = (uint32_t)st * STAGE;
        ld_tile(A0, m0, kt, base + offA0);
        if (NT == 3) ld_tile(A1, m0, kt, base + offA1);
        ld_tile(B0, n0, kt, base + offB0);
        ld_tile(B1, n0, kt, base + offB1);
    };

    float acc[2][8][4];
    #pragma unroll
    for (int mf = 0; mf < 2; ++mf)
        #pragma unroll
        for (int nf = 0; nf < 8; ++nf)
            #pragma unroll
            for (int i = 0; i < 4; ++i) acc[mf][nf][i] = 0.f;

    // ldmatrix per-thread source coords (within tile)
    const int rowA = wm + (ln & 15);               // + mf*16
    const int ucA  = (ln >> 4);                    // + k16*2
    const int rowB = wn + ((ln >> 4) << 3) + (ln & 7);   // + nfp*16
    const int ucB  = ((ln >> 3) & 1);              // + k16*2

    load_chunk(0, 0); CP_COMMIT();

    for (int c = 0; c < NC; ++c) {
        if (c + 1 < NC) { load_chunk(c + 1, (c + 1) & 1); CP_COMMIT(); }
        if (c + 1 < NC) asm volatile("cp.async.wait_group 1;" ::: "memory");
        else            asm volatile("cp.async.wait_group 0;" ::: "memory");
        __syncthreads();

        const uint32_t base = sb + (uint32_t)(c & 1) * STAGE;
        #pragma unroll
        for (int k16 = 0; k16 < 4; ++k16) {
            // A fragments (2 m-frags per term)
            uint32_t a0[2][4], a1[2][4];
            #pragma unroll
            for (int mf = 0; mf < 2; ++mf) {
                uint32_t off = swz((uint32_t)((rowA + mf * 16) * 128 + (k16 * 2 + ucA) * 16));
                ldsm_x4(a0[mf][0], a0[mf][1], a0[mf][2], a0[mf][3], base + offA0 + off);
                if (NT == 3)
                    ldsm_x4(a1[mf][0], a1[mf][1], a1[mf][2], a1[mf][3], base + offA1 + off);
            }
            // B fragments (8 n-frags per term; x4 gives 2 n-frags)
            uint32_t b0[8][2], b1[8][2];
            #pragma unroll
            for (int np = 0; np < 4; ++np) {
                uint32_t off = swz((uint32_t)((rowB + np * 16) * 128 + (k16 * 2 + ucB) * 16));
                ldsm_x4(b0[2 * np][0], b0[2 * np][1], b0[2 * np + 1][0], b0[2 * np + 1][1],
                        base + offB0 + off);
                ldsm_x4(b1[2 * np][0], b1[2 * np][1], b1[2 * np + 1][0], b1[2 * np + 1][1],
                        base + offB1 + off);
            }
            #pragma unroll
            for (int mf = 0; mf < 2; ++mf)
                #pragma unroll
                for (int nf = 0; nf < 8; ++nf) {
                    mma16816(acc[mf][nf][0], acc[mf][nf][1], acc[mf][nf][2], acc[mf][nf][3],
                             a0[mf][0], a0[mf][1], a0[mf][2], a0[mf][3],
                             b0[nf][0], b0[nf][1]);
                    mma16816(acc[mf][nf][0], acc[mf][nf][1], acc[mf][nf][2], acc[mf][nf][3],
                             a0[mf][0], a0[mf][1], a0[mf][2], a0[mf][3],
                             b1[nf][0], b1[nf][1]);
                    if (NT == 3)
                        mma16816(acc[mf][nf][0], acc[mf][nf][1], acc[mf][nf][2], acc[mf][nf][3],
                                 a1[mf][0], a1[mf][1], a1[mf][2], a1[mf][3],
                                 b0[nf][0], b0[nf][1]);
                }
        }
        __syncthreads();
    }

    // ---- epilogue ----
    // acc[mf][nf][i]: row = m0+wm+mf*16+(ln>>2)+8*(i>>1), col = n0+wn+nf*8+(ln&3)*2+(i&1)
    if (MODE == 0) {
        #pragma unroll
        for (int mf = 0; mf < 2; ++mf) {
            #pragma unroll
            for (int i2 = 0; i2 < 2; ++i2) {
                const int m = m0 + wm + mf * 16 + (ln >> 2) + 8 * i2;
                #pragma unroll
                for (int nf = 0; nf < 8; ++nf) {
                    #pragma unroll
                    for (int j = 0; j < 2; ++j) {
                        const int n = n0 + wn + nf * 8 + (ln & 3) * 2 + j;
                        float v  = acc[mf][nf][i2 * 2 + j] + bias[n] + t * tvec[n];
                        float hh = tanhf(v);
                        size_t idx = (size_t)m * Hn + n;
                        g_h[idx] = hh;
                        __nv_bfloat16 hi = __float2bfloat16(hh);
                        g_h_hi[idx] = hi;
                        g_h_lo[idx] = __float2bfloat16(hh - __bfloat162float(hi));
                    }
                }
            }
        }
    } else if (MODE == 1) {
        #pragma unroll
        for (int mf = 0; mf < 2; ++mf) {
            #pragma unroll
            for (int i2 = 0; i2 < 2; ++i2) {
                const int m = m0 + wm + mf * 16 + (ln >> 2) + 8 * i2;   // 0..4095
                const int b = m & (Bn - 1);
                float s = 0.f;
                #pragma unroll
                for (int nf = 0; nf < 8; ++nf) {
                    const int ncol = n0 + wn + nf * 8 + (ln & 3) * 2;   // even
                    const float p0 = acc[mf][nf][i2 * 2 + 0];
                    const float p1 = acc[mf][nf][i2 * 2 + 1];
                    const float hh = g_h[(size_t)b * Hn + (ncol >> 1)];
                    s += (1.f - hh * hh) * p0 * p1;
                }
                // reduce over the 4 lanes of the quad (same row)
                s += __shfl_xor_sync(0xffffffffu, s, 1);
                s += __shfl_xor_sync(0xffffffffu, s, 2);
                if ((ln & 3) == 0) atomicAdd(&g_div[m], s);
            }
        }
    } else {
        float* kout = g_kbuf[kid];
        #pragma unroll
        for (int mf = 0; mf < 2; ++mf) {
            #pragma unroll
            for (int i2 = 0; i2 < 2; ++i2) {
                const int m = m0 + wm + mf * 16 + (ln >> 2) + 8 * i2;
                #pragma unroll
                for (int nf = 0; nf < 8; ++nf) {
                    #pragma unroll
                    for (int j = 0; j < 2; ++j) {
                        const int n = n0 + wn + nf * 8 + (ln & 3) * 2 + j;
                        kout[(size_t)m * DP1 + n] = acc[mf][nf][i2 * 2 + j] + bias[n];
                    }
                }
            }
        }
    }
}

// -------------------- host-side key schedule --------------------------------
struct KP { uint32_t a, b; };
static inline KP h_tf(KP k, uint32_t x0, uint32_t x1) {
    KP r; tf2x32(k.a, k.b, x0, x1, r.a, r.b); return r;
}
static inline KP lower_key(KP kq, uint32_t i) {
    KP folded = h_tf(kq, 0u, i);
    return h_tf(folded, 0u, 1u);
}

// -------------------- launcher ----------------------------------------------
extern "C" void kernel_launch(void* const* d_in, const int* in_sizes, int n_in,
                              void* d_out, int out_size)
{
    (void)in_sizes; (void)n_in; (void)out_size;
    const float* x   = (const float*)d_in[0];
    const float* W1  = (const float*)d_in[1];
    const float* b1  = (const float*)d_in[2];
    const float* tw1 = (const float*)d_in[3];
    const float* W2  = (const float*)d_in[4];
    const float* b2  = (const float*)d_in[5];
    float* out = (float*)d_out;

    constexpr int SM3 = 2 * 4 * TILE_B;   // 3-term: 128 KB
    constexpr int SM2 = 2 * 3 * TILE_B;   // 2-term: 96 KB
    static bool attr_done = false;
    if (!attr_done) {
        cudaFuncSetAttribute(gemm_mma<0>, cudaFuncAttributeMaxDynamicSharedMemorySize, SM3);
        cudaFuncSetAttribute(gemm_mma<1>, cudaFuncAttributeMaxDynamicSharedMemorySize, SM2);
        cudaFuncSetAttribute(gemm_mma<2>, cudaFuncAttributeMaxDynamicSharedMemorySize, SM3);
        attr_done = true;
    }

    const int GRID_E = (Bn * DP1 + 255) / 256;
    const int GRID_Z = (Bn * Dn + 255) / 256;

    init_state_kernel<<<GRID_E, 256>>>(x);
    prep_weights_kernel<<<(Hn * Dn + 255) / 256, 256>>>(W1, W2);

    const float step = (float)(1.0 / 9.0);
    KP key{ 0u, 1234u };

    for (int s = 0; s < 9; ++s) {
        const float t0 = (float)s * step;
        const float t1 = (float)(s + 1) * step;
        const float dt = t1 - t0;
        KP ks5[5];
        for (uint32_t j = 0; j < 5; ++j) ks5[j] = h_tf(key, 0u, j);
        key = ks5[0];
        const float tst[4] = { t0, t0 + dt / 3.0f, t0 + dt * 2.0f / 3.0f, t1 };

        for (int st = 0; st < 4; ++st) {
            KP l0 = lower_key(ks5[1 + st], 0u);
            KP l1 = lower_key(ks5[1 + st], 1u);
            rng_kernel<<<GRID_Z, 256>>>(l0.a, l0.b, l1.a, l1.b);

            if (st == 0)      split_state_kernel<<<GRID_Z, 256>>>();
            else if (st == 1) prep_split_kernel<<<GRID_Z, 256>>>(dt / 3.f, 0.f, 0.f);
            else if (st == 2) prep_split_kernel<<<GRID_Z, 256>>>(-dt / 3.f, dt, 0.f);
            else              prep_split_kernel<<<GRID_Z, 256>>>(dt, -dt, dt);

            // h = tanh(z@W1 + b1 + t*tw1)
            gemm_mma<0><<<dim3(Hn / 128, Bn / 128), 256, SM3>>>(b1, tw1, tst[st], 0);
            // Hutchinson: acc pairs (e@W1, e@W2^T) interleaved, fused div
            gemm_mma<1><<<dim3(2 * Hn / 128, 2 * Bn / 128), 256, SM2>>>(nullptr, nullptr, 0.f, 0);
            // f = h@W2 + b2 -> k[st][:, :D]
            gemm_mma<2><<<dim3(Dn / 128, Bn / 128), 256, SM3>>>(b2, nullptr, 0.f, st);
            // k[st][:, D] = -clip((div0+div1)/2)
            div_fin_kernel<<<(Bn + 255) / 256, 256>>>(st);
        }
        update_kernel<<<GRID_E, 256>>>(dt * 0.125f);
    }

    finalize_kernel<<<Bn, 256>>>(out);
}

// round 4
// speedup vs baseline: 3.7832x; 1.2141x over previous
#include <cuda_runtime.h>
#include <cuda_bf16.h>
#include <cstdint>

// ============================================================================
// FloReLBlock via mma.sync split-bf16 GEMMs (tcgen05 unavailable: harness
// targets compute_103 without 'a'). R4: 2 CTAs/SM (K-chunk 32, SW64 tiles),
// fat kernel fusing GEMM2+GEMM3, fused elementwise stages.
// ============================================================================

constexpr int Bn  = 2048;
constexpr int Dn  = 512;
constexpr int Hn  = 1024;
constexpr int DP1 = Dn + 1;

// -------------------- device scratch ----------------------------------------
__device__ float g_state[Bn * DP1];
__device__ float g_kbuf[4][Bn * DP1];
__device__ float g_h[Bn * Hn];
__device__ float g_div[5 * 2 * Bn];        // slices: 0..4 (stage0 double-buffered 0/4)

__device__ __align__(16) __nv_bfloat16 g_z_hi[Bn * Dn];
__device__ __align__(16) __nv_bfloat16 g_z_lo[Bn * Dn];
__device__ __align__(16) __nv_bfloat16 g_e   [2 * Bn * Dn];
__device__ __align__(16) __nv_bfloat16 g_h_hi[Bn * Hn];
__device__ __align__(16) __nv_bfloat16 g_h_lo[Bn * Hn];
__device__ __align__(16) __nv_bfloat16 g_W1T_hi[Hn * Dn];      // [H x D] (N x K)
__device__ __align__(16) __nv_bfloat16 g_W1T_lo[Hn * Dn];
__device__ __align__(16) __nv_bfloat16 g_Wc_hi[2 * Hn * Dn];   // interleaved W1T/W2 rows
__device__ __align__(16) __nv_bfloat16 g_Wc_lo[2 * Hn * Dn];
__device__ __align__(16) __nv_bfloat16 g_W2T_hi[Dn * Hn];      // [D x H] (N x K)
__device__ __align__(16) __nv_bfloat16 g_W2T_lo[Dn * Hn];

// -------------------- threefry2x32 (exact JAX, partitionable) ---------------
__host__ __device__ __forceinline__ void tf2x32(
    uint32_t k0, uint32_t k1, uint32_t x0, uint32_t x1,
    uint32_t& o0, uint32_t& o1)
{
    const uint32_t ks0 = k0;
    const uint32_t ks1 = k1;
    const uint32_t ks2 = 0x1BD11BDAu ^ k0 ^ k1;
    x0 += ks0; x1 += ks1;
#define TFR(r) { x0 += x1; x1 = (x1 << (r)) | (x1 >> (32 - (r))); x1 ^= x0; }
    TFR(13) TFR(15) TFR(26) TFR(6)
    x0 += ks1; x1 += ks2 + 1u;
    TFR(17) TFR(29) TFR(16) TFR(24)
    x0 += ks2; x1 += ks0 + 2u;
    TFR(13) TFR(15) TFR(26) TFR(6)
    x0 += ks0; x1 += ks1 + 3u;
    TFR(17) TFR(29) TFR(16) TFR(24)
    x0 += ks1; x1 += ks2 + 4u;
    TFR(13) TFR(15) TFR(26) TFR(6)
    x0 += ks2; x1 += ks0 + 5u;
#undef TFR
    o0 = x0; o1 = x1;
}

// -------------------- helpers -----------------------------------------------
__device__ __forceinline__ void split2(float v, __nv_bfloat16& hi, __nv_bfloat16& lo) {
    hi = __float2bfloat16(v);
    lo = __float2bfloat16(v - __bfloat162float(hi));
}

__device__ __forceinline__ uint32_t smem_u32(const void* p) {
    uint32_t a;
    asm("{ .reg .u64 t; cvta.to.shared.u64 t, %1; cvt.u32.u64 %0, t; }" : "=r"(a) : "l"(p));
    return a;
}

__device__ __forceinline__ void cpasync16(uint32_t dst, const void* src) {
    asm volatile("cp.async.cg.shared.global [%0], [%1], 16;" :: "r"(dst), "l"(src));
}
#define CP_COMMIT() asm volatile("cp.async.commit_group;" ::: "memory")

__device__ __forceinline__ uint32_t swz64(uint32_t x) {   // 64B-row swizzle
    return x ^ ((x >> 3) & 0x30u);
}

__device__ __forceinline__ void ldsm_x4(uint32_t& r0, uint32_t& r1, uint32_t& r2, uint32_t& r3, uint32_t addr) {
    asm volatile("ldmatrix.sync.aligned.m8n8.x4.shared.b16 {%0,%1,%2,%3}, [%4];"
                 : "=r"(r0), "=r"(r1), "=r"(r2), "=r"(r3) : "r"(addr));
}

__device__ __forceinline__ void mma16816(
    float* d, const uint32_t* a, const uint32_t* b)
{
    asm volatile(
        "mma.sync.aligned.m16n8k16.row.col.f32.bf16.bf16.f32 "
        "{%0,%1,%2,%3}, {%4,%5,%6,%7}, {%8,%9}, {%0,%1,%2,%3};"
        : "+f"(d[0]), "+f"(d[1]), "+f"(d[2]), "+f"(d[3])
        : "r"(a[0]), "r"(a[1]), "r"(a[2]), "r"(a[3]), "r"(b[0]), "r"(b[1]));
}

__device__ __forceinline__ float blockReduceSum256(float v) {
    __shared__ float sh[8];
    #pragma unroll
    for (int o = 16; o > 0; o >>= 1) v += __shfl_down_sync(0xffffffffu, v, o);
    const int lane = threadIdx.x & 31;
    const int w    = threadIdx.x >> 5;
    if (lane == 0) sh[w] = v;
    __syncthreads();
    if (w == 0) {
        v = (lane < 8) ? sh[lane] : 0.f;
        #pragma unroll
        for (int o = 4; o > 0; o >>= 1) v += __shfl_down_sync(0xffffffffu, v, o);
    }
    return v;
}

__device__ __forceinline__ __nv_bfloat16 rad_bf16(uint32_t bits) {
    return __float2bfloat16((bits & 1u) ? 1.f : -1.f);
}

// -------------------- elementwise kernels -----------------------------------
__global__ void __launch_bounds__(256) prep_weights_kernel(
    const float* __restrict__ W1, const float* __restrict__ W2)
{
    int i = blockIdx.x * 256 + threadIdx.x;
    if (i < Hn * Dn) {
        int j = i / Dn, d = i % Dn;
        __nv_bfloat16 hi, lo;
        split2(W1[(size_t)d * Hn + j], hi, lo);
        g_W1T_hi[(size_t)j * Dn + d] = hi;
        g_W1T_lo[(size_t)j * Dn + d] = lo;
        g_Wc_hi[(size_t)(2 * j) * Dn + d] = hi;
        g_Wc_lo[(size_t)(2 * j) * Dn + d] = lo;
        split2(W2[(size_t)j * Dn + d], hi, lo);
        g_Wc_hi[(size_t)(2 * j + 1) * Dn + d] = hi;
        g_Wc_lo[(size_t)(2 * j + 1) * Dn + d] = lo;
        g_W2T_hi[(size_t)d * Hn + j] = hi;
        g_W2T_lo[(size_t)d * Hn + j] = lo;
    }
}

// init: state from x, z-split, rng for step0/stage0, zero div slice 0
__global__ void __launch_bounds__(256) init_kernel(
    const float* __restrict__ x,
    uint32_t a0, uint32_t b0, uint32_t a1, uint32_t b1)
{
    int i = blockIdx.x * 256 + threadIdx.x;
    if (i < 2 * Bn) g_div[i] = 0.f;
    if (i >= Bn * DP1) return;
    int b = i / DP1, c = i % DP1;
    float v = (c < Dn) ? x[b * Dn + c] : 0.f;
    g_state[i] = v;
    if (c < Dn) {
        int j = b * Dn + c;
        split2(v, g_z_hi[j], g_z_lo[j]);
        uint32_t o0, o1;
        tf2x32(a0, b0, 0u, (uint32_t)j, o0, o1);
        g_e[j] = rad_bf16(o0 ^ o1);
        tf2x32(a1, b1, 0u, (uint32_t)j, o0, o1);
        g_e[Bn * Dn + j] = rad_bf16(o0 ^ o1);
    }
}

// stage st>0: z = state + c1*k1 + c2*k2 + c3*k3, split, rng, zero div slice
__global__ void __launch_bounds__(256) stage_prep_kernel(
    float c1, float c2, float c3,
    uint32_t a0, uint32_t b0, uint32_t a1, uint32_t b1, int divslot)
{
    int i = blockIdx.x * 256 + threadIdx.x;
    if (i < 2 * Bn) g_div[divslot * 2 * Bn + i] = 0.f;
    if (i >= Bn * Dn) return;
    int b = i >> 9, d = i & 511;
    int idx = b * DP1 + d;
    float v = g_state[idx] + c1 * g_kbuf[0][idx] + c2 * g_kbuf[1][idx] + c3 * g_kbuf[2][idx];
    split2(v, g_z_hi[i], g_z_lo[i]);
    uint32_t o0, o1;
    tf2x32(a0, b0, 0u, (uint32_t)i, o0, o1);
    g_e[i] = rad_bf16(o0 ^ o1);
    tf2x32(a1, b1, 0u, (uint32_t)i, o0, o1);
    g_e[Bn * Dn + i] = rad_bf16(o0 ^ o1);
}

// end of step: state update (incl. div col), then next-step stage0 prep
__global__ void __launch_bounds__(256) update_prep_kernel(
    float w, int slot0_cur, int slot0_next,
    uint32_t a0, uint32_t b0, uint32_t a1, uint32_t b1)
{
    int i = blockIdx.x * 256 + threadIdx.x;
    if (i < 2 * Bn) g_div[slot0_next * 2 * Bn + i] = 0.f;   // other buffer: no race
    if (i >= Bn * DP1) return;
    int b = i / DP1, c = i % DP1;
    if (c < Dn) {
        float delta = g_kbuf[0][i] + 3.f * (g_kbuf[1][i] + g_kbuf[2][i]) + g_kbuf[3][i];
        float v = g_state[i] + w * delta;
        g_state[i] = v;
        int j = b * Dn + c;
        split2(v, g_z_hi[j], g_z_lo[j]);
        uint32_t o0, o1;
        tf2x32(a0, b0, 0u, (uint32_t)j, o0, o1);
        g_e[j] = rad_bf16(o0 ^ o1);
        tf2x32(a1, b1, 0u, (uint32_t)j, o0, o1);
        g_e[Bn * Dn + j] = rad_bf16(o0 ^ o1);
    } else {
        const float coef[4] = {1.f, 3.f, 3.f, 1.f};
        float comb = 0.f;
        #pragma unroll
        for (int st = 0; st < 4; ++st) {
            int slot = (st == 0) ? slot0_cur : st;
            float dv = 0.5f * (g_div[slot * 2 * Bn + b] + g_div[slot * 2 * Bn + Bn + b]);
            dv = fminf(fmaxf(dv, -100.f), 100.f);
            comb += coef[st] * (-dv);
        }
        g_state[i] += w * comb;
    }
}

__global__ void __launch_bounds__(256) finalize_kernel(float* __restrict__ out) {
    const int b = blockIdx.x;
    const float* row = g_state + (size_t)b * DP1;
    float acc = 0.f;
    for (int d = threadIdx.x; d < Dn; d += 256) {
        float v = row[d];
        out[(size_t)b * Dn + d] = v;
        acc += v * v;
    }
    float tot = blockReduceSum256(acc);
    if (threadIdx.x == 0)
        out[(size_t)Bn * Dn + b] = -0.5f * tot + row[Dn];
}

// -------------------- mma.sync GEMM body ------------------------------------
// CTA tile 128x128, K-chunk 32 (64B rows, SW64 swizzle), 8 warps (4Mx2N,
// warp tile 32x64), double buffered.
// MODE 0: h = tanh(acc + b1 + t*tw1), K=512, 3 terms
// MODE 1: Hutchinson div (interleaved Wc), K=512, 2 terms -> g_div[slot]
// MODE 2: k = acc + b2, K=1024, 3 terms -> g_kbuf[arg]
constexpr int TILE_B = 8192;   // 128 rows x 64 bytes

template <int MODE>
__device__ __forceinline__ void gemm_body(
    int bx, int by, const float* __restrict__ bias,
    const float* __restrict__ tvec, float t, int arg, char* smem)
{
    constexpr int K  = (MODE == 2) ? 1024 : 512;
    constexpr int NC = K / 32;
    constexpr int NT = (MODE == 1) ? 2 : 3;
    constexpr int NTILES = (NT == 3) ? 4 : 3;
    constexpr int STAGE = NTILES * TILE_B;

    const uint32_t sb = smem_u32(smem);
    const int tid = threadIdx.x;
    const int wid = tid >> 5;
    const int ln  = tid & 31;
    const int m0  = by * 128;
    const int n0  = bx * 128;
    const int wm  = (wid >> 1) * 32;
    const int wn  = (wid & 1) * 64;

    const __nv_bfloat16 *A0, *A1, *B0, *B1;
    if (MODE == 0)      { A0 = g_z_hi; A1 = g_z_lo;  B0 = g_W1T_hi; B1 = g_W1T_lo; }
    else if (MODE == 1) { A0 = g_e;    A1 = nullptr; B0 = g_Wc_hi;  B1 = g_Wc_lo;  }
    else                { A0 = g_h_hi; A1 = g_h_lo;  B0 = g_W2T_hi; B1 = g_W2T_lo; }

    constexpr uint32_t offA0 = 0;
    constexpr uint32_t offA1 = (NT == 3) ? TILE_B : 0;
    constexpr uint32_t offB0 = (NT == 3) ? 2 * TILE_B : TILE_B;
    constexpr uint32_t offB1 = offB0 + TILE_B;

    // tile loader: 128 rows x 32 bf16 (64B rows): 512 x 16B units, 2 iters
    auto ld_tile = [&](const __nv_bfloat16* g, int rbase, int kt, uint32_t toff) {
        #pragma unroll
        for (int it = 0; it < 2; ++it) {
            int idx = it * 256 + tid;
            int row = idx >> 2, u = idx & 3;
            uint32_t dst = sb + toff + swz64((uint32_t)(row * 64 + u * 16));
            cpasync16(dst, (const void*)(g + (size_t)(rbase + row) * K + kt + u * 8));
        }
    };
    auto load_chunk = [&](int c, int st) {
        const int kt = c * 32;
        const uint32_t base = (uint32_t)st * STAGE;
        ld_tile(A0, m0, kt, base + offA0);
        if (NT == 3) ld_tile(A1, m0, kt, base + offA1);
        ld_tile(B0, n0, kt, base + offB0);
        ld_tile(B1, n0, kt, base + offB1);
    };

    float acc[2][8][4];
    #pragma unroll
    for (int mf = 0; mf < 2; ++mf)
        #pragma unroll
        for (int nf = 0; nf < 8; ++nf)
            #pragma unroll
            for (int i = 0; i < 4; ++i) acc[mf][nf][i] = 0.f;

    const int rowA = wm + (ln & 15);
    const int ucA  = (ln >> 4);
    const int rowB = wn + ((ln >> 4) << 3) + (ln & 7);
    const int ucB  = ((ln >> 3) & 1);

    load_chunk(0, 0); CP_COMMIT();

    for (int c = 0; c < NC; ++c) {
        if (c + 1 < NC) { load_chunk(c + 1, (c + 1) & 1); CP_COMMIT(); }
        if (c + 1 < NC) asm volatile("cp.async.wait_group 1;" ::: "memory");
        else            asm volatile("cp.async.wait_group 0;" ::: "memory");
        __syncthreads();

        const uint32_t base = sb + (uint32_t)(c & 1) * STAGE;
        #pragma unroll
        for (int k16 = 0; k16 < 2; ++k16) {
            uint32_t a0[2][4], a1[2][4];
            #pragma unroll
            for (int mf = 0; mf < 2; ++mf) {
                uint32_t off = swz64((uint32_t)((rowA + mf * 16) * 64 + (k16 * 2 + ucA) * 16));
                ldsm_x4(a0[mf][0], a0[mf][1], a0[mf][2], a0[mf][3], base + offA0 + off);
                if (NT == 3)
                    ldsm_x4(a1[mf][0], a1[mf][1], a1[mf][2], a1[mf][3], base + offA1 + off);
            }
            #pragma unroll
            for (int np = 0; np < 4; ++np) {
                uint32_t b0[2][2], b1[2][2];
                uint32_t off = swz64((uint32_t)((rowB + np * 16) * 64 + (k16 * 2 + ucB) * 16));
                ldsm_x4(b0[0][0], b0[0][1], b0[1][0], b0[1][1], base + offB0 + off);
                ldsm_x4(b1[0][0], b1[0][1], b1[1][0], b1[1][1], base + offB1 + off);
                #pragma unroll
                for (int mf = 0; mf < 2; ++mf)
                    #pragma unroll
                    for (int nl = 0; nl < 2; ++nl) {
                        const int nf = 2 * np + nl;
                        mma16816(acc[mf][nf], a0[mf], b0[nl]);
                        mma16816(acc[mf][nf], a0[mf], b1[nl]);
                        if (NT == 3) mma16816(acc[mf][nf], a1[mf], b0[nl]);
                    }
            }
        }
        __syncthreads();
    }

    // ---- epilogue ----
    if (MODE == 0) {
        #pragma unroll
        for (int mf = 0; mf < 2; ++mf) {
            #pragma unroll
            for (int i2 = 0; i2 < 2; ++i2) {
                const int m = m0 + wm + mf * 16 + (ln >> 2) + 8 * i2;
                #pragma unroll
                for (int nf = 0; nf < 8; ++nf) {
                    #pragma unroll
                    for (int j = 0; j < 2; ++j) {
                        const int n = n0 + wn + nf * 8 + (ln & 3) * 2 + j;
                        float v  = acc[mf][nf][i2 * 2 + j] + bias[n] + t * tvec[n];
                        float hh = tanhf(v);
                        size_t idx = (size_t)m * Hn + n;
                        g_h[idx] = hh;
                        __nv_bfloat16 hi = __float2bfloat16(hh);
                        g_h_hi[idx] = hi;
                        g_h_lo[idx] = __float2bfloat16(hh - __bfloat162float(hi));
                    }
                }
            }
        }
    } else if (MODE == 1) {
        #pragma unroll
        for (int mf = 0; mf < 2; ++mf) {
            #pragma unroll
            for (int i2 = 0; i2 < 2; ++i2) {
                const int m = m0 + wm + mf * 16 + (ln >> 2) + 8 * i2;
                const int b = m & (Bn - 1);
                float s = 0.f;
                #pragma unroll
                for (int nf = 0; nf < 8; ++nf) {
                    const int ncol = n0 + wn + nf * 8 + (ln & 3) * 2;
                    const float p0 = acc[mf][nf][i2 * 2 + 0];
                    const float p1 = acc[mf][nf][i2 * 2 + 1];
                    const float hh = g_h[(size_t)b * Hn + (ncol >> 1)];
                    s += (1.f - hh * hh) * p0 * p1;
                }
                s += __shfl_xor_sync(0xffffffffu, s, 1);
                s += __shfl_xor_sync(0xffffffffu, s, 2);
                if ((ln & 3) == 0) atomicAdd(&g_div[arg * 2 * Bn + m], s);
            }
        }
    } else {
        float* kout = g_kbuf[arg];
        #pragma unroll
        for (int mf = 0; mf < 2; ++mf) {
            #pragma unroll
            for (int i2 = 0; i2 < 2; ++i2) {
                const int m = m0 + wm + mf * 16 + (ln >> 2) + 8 * i2;
                #pragma unroll
                for (int nf = 0; nf < 8; ++nf) {
                    #pragma unroll
                    for (int j = 0; j < 2; ++j) {
                        const int n = n0 + wn + nf * 8 + (ln & 3) * 2 + j;
                        kout[(size_t)m * DP1 + n] = acc[mf][nf][i2 * 2 + j] + bias[n];
                    }
                }
            }
        }
    }
}

// GEMM1: grid (8, 16)
__global__ void __launch_bounds__(256, 2) gemm1_kernel(
    const float* __restrict__ b1, const float* __restrict__ tw1, float t)
{
    extern __shared__ __align__(128) char smem[];
    gemm_body<0>(blockIdx.x, blockIdx.y, b1, tw1, t, 0, smem);
}

// FAT: blocks [0,512) = GEMM2 (div slot), [512,576) = GEMM3 (kbuf kid)
__global__ void __launch_bounds__(256, 2) gemm_fat_kernel(
    const float* __restrict__ b2, int kid, int divslot)
{
    extern __shared__ __align__(128) char smem[];
    const int bid = blockIdx.x;
    if (bid < 512) {
        gemm_body<1>(bid & 15, bid >> 4, nullptr, nullptr, 0.f, divslot, smem);
    } else {
        const int r = bid - 512;
        gemm_body<2>(r & 3, r >> 2, b2, nullptr, 0.f, kid, smem);
    }
}

// -------------------- host-side key schedule --------------------------------
struct KP { uint32_t a, b; };
static inline KP h_tf(KP k, uint32_t x0, uint32_t x1) {
    KP r; tf2x32(k.a, k.b, x0, x1, r.a, r.b); return r;
}
static inline KP lower_key(KP kq, uint32_t i) {
    KP folded = h_tf(kq, 0u, i);
    return h_tf(folded, 0u, 1u);
}

// -------------------- launcher ----------------------------------------------
extern "C" void kernel_launch(void* const* d_in, const int* in_sizes, int n_in,
                              void* d_out, int out_size)
{
    (void)in_sizes; (void)n_in; (void)out_size;
    const float* x   = (const float*)d_in[0];
    const float* W1  = (const float*)d_in[1];
    const float* b1  = (const float*)d_in[2];
    const float* tw1 = (const float*)d_in[3];
    const float* W2  = (const float*)d_in[4];
    const float* b2  = (const float*)d_in[5];
    float* out = (float*)d_out;

    constexpr int SM3 = 2 * 4 * TILE_B;   // 64 KB (3-term; fat uses this too)
    static bool attr_done = false;
    if (!attr_done) {
        cudaFuncSetAttribute(gemm1_kernel,    cudaFuncAttributeMaxDynamicSharedMemorySize, SM3);
        cudaFuncSetAttribute(gemm_fat_kernel, cudaFuncAttributeMaxDynamicSharedMemorySize, SM3);
        attr_done = true;
    }

    // key schedule for all steps (host, deterministic)
    KP lk[10][4][2];      // [step][stage][sample]; step 9 = dummy
    {
        KP key{ 0u, 1234u };
        for (int s = 0; s < 9; ++s) {
            KP ks5[5];
            for (uint32_t j = 0; j < 5; ++j) ks5[j] = h_tf(key, 0u, j);
            key = ks5[0];
            for (int st = 0; st < 4; ++st) {
                lk[s][st][0] = lower_key(ks5[1 + st], 0u);
                lk[s][st][1] = lower_key(ks5[1 + st], 1u);
            }
        }
        for (int st = 0; st < 4; ++st)
            lk[9][st][0] = lk[9][st][1] = KP{0u, 0u};
    }

    const int GRID_E = (Bn * DP1 + 255) / 256;
    const int GRID_Z = (Bn * Dn + 255) / 256;
    const float step = (float)(1.0 / 9.0);

    prep_weights_kernel<<<(Hn * Dn + 255) / 256, 256>>>(W1, W2);
    init_kernel<<<GRID_E, 256>>>(x, lk[0][0][0].a, lk[0][0][0].b, lk[0][0][1].a, lk[0][0][1].b);

    for (int s = 0; s < 9; ++s) {
        const float t0 = (float)s * step;
        const float t1 = (float)(s + 1) * step;
        const float dt = t1 - t0;
        const float tst[4] = { t0, t0 + dt / 3.0f, t0 + dt * 2.0f / 3.0f, t1 };
        const int slot0_cur  = (s & 1) ? 4 : 0;
        const int slot0_next = (s & 1) ? 0 : 4;

        for (int st = 0; st < 4; ++st) {
            if (st > 0) {
                float c1 = 0.f, c2 = 0.f, c3 = 0.f;
                if (st == 1)      { c1 = dt / 3.f; }
                else if (st == 2) { c1 = -dt / 3.f; c2 = dt; }
                else              { c1 = dt; c2 = -dt; c3 = dt; }
                stage_prep_kernel<<<GRID_Z, 256>>>(
                    c1, c2, c3,
                    lk[s][st][0].a, lk[s][st][0].b, lk[s][st][1].a, lk[s][st][1].b, st);
            }
            const int divslot = (st == 0) ? slot0_cur : st;
            gemm1_kernel<<<dim3(8, 16), 256, SM3>>>(b1, tw1, tst[st]);
            gemm_fat_kernel<<<576, 256, SM3>>>(b2, st, divslot);
        }
        update_prep_kernel<<<GRID_E, 256>>>(
            dt * 0.125f, slot0_cur, slot0_next,
            lk[s + 1][0][0].a, lk[s + 1][0][0].b, lk[s + 1][0][1].a, lk[s + 1][0][1].b);
    }

    finalize_kernel<<<Bn, 256>>>(out);
}